// round 13
// baseline (speedup 1.0000x reference)
#include <cuda_runtime.h>
#include <cuda_fp16.h>
#include <cstdint>

#define BB 16
#define RR 1024
#define TT 512
#define DD 1024
#define HH 1024

typedef __half h16;

// ---------------------------------------------------------------------------
// Scratch (__device__ globals; allocation-free rule)
// ---------------------------------------------------------------------------
__device__ h16 g_region_h[BB*RR*DD], g_region_l[BB*RR*DD];
__device__ h16 g_query_h [BB*TT*DD], g_query_l [BB*TT*DD];
__device__ h16 g_Wr_h[DD*HH], g_Wr_l[DD*HH];
__device__ h16 g_Wq_h[DD*HH], g_Wq_l[DD*HH];
__device__ h16 g_Mt_h[DD*DD], g_Mt_l[DD*DD];        // Mt2 = Wr @ Wq^T
__device__ h16 g_Qp_h[BB*TT*DD], g_Qp_l[BB*TT*DD];  // Qp = query @ Mt2^T
__device__ h16 g_qT_h[BB*DD*TT], g_qT_l[BB*DD*TT];  // query^T [B][D][T]
__device__ h16 g_attn_e[BB*RR*TT];                  // unnormalized exp (fp16)
__device__ float g_scores[BB*RR*TT];                // ALSO reused: first 4*DD*DD floats = Mt split-K partials
__device__ float g_invden[BB*RR];
__device__ float g_u[BB*RR];
__device__ float g_v[BB*TT];
__device__ float g_wrbq[DD];
__device__ float g_wqbr[DD];
__device__ float g_c[1];

// ---------------------------------------------------------------------------
// PTX helpers (sm_80-compatible; compiles for compute_103 virtual arch)
// ---------------------------------------------------------------------------
__device__ __forceinline__ uint32_t smem_u32(const void* p) {
    uint32_t a;
    asm("{ .reg .u64 t; cvta.to.shared.u64 t, %1; cvt.u32.u64 %0, t; }" : "=r"(a) : "l"(p));
    return a;
}
#define CP_ASYNC16(dst, src) \
    asm volatile("cp.async.cg.shared.global [%0], [%1], 16;" :: "r"(dst), "l"(src))
#define CP_COMMIT() asm volatile("cp.async.commit_group;" ::: "memory")
#define CP_WAIT2()  asm volatile("cp.async.wait_group 2;" ::: "memory")
#define CP_WAIT1()  asm volatile("cp.async.wait_group 1;" ::: "memory")
#define CP_WAIT0()  asm volatile("cp.async.wait_group 0;" ::: "memory")

__device__ __forceinline__ void ldsm4(uint32_t* r, uint32_t addr) {
    asm volatile("ldmatrix.sync.aligned.m8n8.x4.shared.b16 {%0,%1,%2,%3}, [%4];"
                 : "=r"(r[0]), "=r"(r[1]), "=r"(r[2]), "=r"(r[3]) : "r"(addr));
}
// fp16 inputs, f32 accumulate
__device__ __forceinline__ void mma_f32acc(float* d, const uint32_t* a, const uint32_t* b) {
    asm volatile("mma.sync.aligned.m16n8k16.row.col.f32.f16.f16.f32 "
                 "{%0,%1,%2,%3}, {%4,%5,%6,%7}, {%8,%9}, {%0,%1,%2,%3};"
                 : "+f"(d[0]), "+f"(d[1]), "+f"(d[2]), "+f"(d[3])
                 : "r"(a[0]), "r"(a[1]), "r"(a[2]), "r"(a[3]), "r"(b[0]), "r"(b[1]));
}
// fp16 inputs, fp16 accumulate (correction phases)
__device__ __forceinline__ void mma_f16acc(uint32_t* d, const uint32_t* a, const uint32_t* b) {
    asm volatile("mma.sync.aligned.m16n8k16.row.col.f16.f16.f16.f16 "
                 "{%0,%1}, {%2,%3,%4,%5}, {%6,%7}, {%0,%1};"
                 : "+r"(d[0]), "+r"(d[1])
                 : "r"(a[0]), "r"(a[1]), "r"(a[2]), "r"(a[3]), "r"(b[0]), "r"(b[1]));
}

// ---------------------------------------------------------------------------
// fp16 multi-phase GEMM (NT): C = sum over NPH phases; corrections FIRST
//   NPH=3: phases { Ah*Bl (f16acc), Al*Bh (f16acc), Ah*Bh (f32acc) }
//   NPH=2: phases { Ah*Bl (f16acc), Ah*Bh (f32acc) }
// Block 128x128, BK=32, 4 warps (64x64 warp tile), 4-stage cp.async.
// EPI: 0 = plain fp32 store to Cf + z*sC (split-K partials; z also offsets A/B);
//      1 = fp16 hi/lo split store; 2 = fp32 + u[m] + v[n];
//      3 = fused scorer: atomicAdd out[r] += invden[r]*sum_c C*(Ws2+region*Ws3)
// ---------------------------------------------------------------------------
#define STAGE_B 20480
#define NSTAGE  4
#define SMEM_GEMM (NSTAGE * STAGE_B)   // 80 KB dynamic

template <int EPI, int NPH>
__global__ __launch_bounds__(128, 2) void gemm3_f16(
    const h16* __restrict__ Ah, const h16* __restrict__ Al,
    const h16* __restrict__ Bh, const h16* __restrict__ Bl,
    float* __restrict__ Cf, h16* __restrict__ Chi, h16* __restrict__ Clo,
    const float* __restrict__ uvec, const float* __restrict__ vvec,
    const float* __restrict__ regionF, const float* __restrict__ WsP,
    float* __restrict__ outP,
    int Kbase, int lda, int ldb, int ldc,
    long sA, long sB, long sC, int uStr, int vStr)
{
    extern __shared__ __align__(16) uint8_t smem_raw[];
    const int tid = threadIdx.x;
    const int wid = tid >> 5, l = tid & 31;
    const int wm = wid >> 1, wn = wid & 1;
    const int blockM = blockIdx.y * 128, blockN = blockIdx.x * 128;
    const int z = blockIdx.z;

    Ah += (long)z * sA;  Al += (long)z * sA;
    Bh += (long)z * sB;  Bl += (long)z * sB;

    const uint32_t smBase = smem_u32(smem_raw);
    const int cpb = Kbase / 32;
    const int NK  = NPH * cpb;
    const int mainStart = (NPH - 1) * cpb;   // first kb of the f32-acc main phase

    const uint32_t aF = smBase +
        (uint32_t)((wm * 64 + (l & 15)) * 80 + ((l >> 4) * 16));
    const int bn = (l & 7) + ((l & 16) >> 1);
    const uint32_t bF = smBase + 10240u +
        (uint32_t)((wn * 64 + bn) * 80 + (((l >> 3) & 1) * 16));

    // fp16 accumulators for correction phases (2 regs per 16x8 tile)
    uint32_t acc2[4][8][2];
#pragma unroll
    for (int i = 0; i < 4; i++)
#pragma unroll
        for (int j = 0; j < 8; j++) { acc2[i][j][0] = 0u; acc2[i][j][1] = 0u; }

    float acc[4][8][4];   // written at phase boundary, then f32-acc main phase

    const int lr = tid >> 2, lj = tid & 3;

    auto load_stage = [&](int stage, int kb) {
        const int ph  = kb / cpb;
        const int kbl = kb - ph * cpb;
        const h16* Ap = (NPH == 3 && ph == 1) ? Al : Ah;
        const h16* Bp = (ph == 0) ? Bl : Bh;
        const int k0 = kbl * 32;
        const uint32_t sa = smBase + stage * STAGE_B;
        const uint32_t sb = sa + 10240u;
#pragma unroll
        for (int it = 0; it < 4; it++) {
            const int rr = lr + it * 32;
            const h16* ga = Ap + (long)(blockM + rr) * lda + k0 + lj * 8;
            CP_ASYNC16(sa + (uint32_t)(rr * 80 + lj * 16), ga);
            const h16* gb = Bp + (long)(blockN + rr) * ldb + k0 + lj * 8;
            CP_ASYNC16(sb + (uint32_t)(rr * 80 + lj * 16), gb);
        }
        CP_COMMIT();
    };

    load_stage(0, 0);
    load_stage(1, 1);
    load_stage(2, 2);

    for (int kb = 0; kb < NK; kb++) {
        if (kb < NK - 2)       CP_WAIT2();
        else if (kb == NK - 2) CP_WAIT1();
        else                   CP_WAIT0();
        __syncthreads();
        if (kb + 3 < NK) load_stage((kb + 3) & 3, kb + 3);

        if (kb == mainStart) {
            // phase boundary: convert fp16 correction sums into f32 accumulators
#pragma unroll
            for (int i = 0; i < 4; i++)
#pragma unroll
                for (int j = 0; j < 8; j++) {
                    __half2 p0 = *reinterpret_cast<__half2*>(&acc2[i][j][0]);
                    __half2 p1 = *reinterpret_cast<__half2*>(&acc2[i][j][1]);
                    float2 f0 = __half22float2(p0);
                    float2 f1 = __half22float2(p1);
                    acc[i][j][0] = f0.x;  acc[i][j][1] = f0.y;
                    acc[i][j][2] = f1.x;  acc[i][j][3] = f1.y;
                }
        }

        const uint32_t so = (uint32_t)(kb & 3) * STAGE_B;
        const bool isCorr = kb < mainStart;
#pragma unroll
        for (int ks = 0; ks < 2; ks++) {
            uint32_t af[4][4], bfr[4][4];
#pragma unroll
            for (int i = 0; i < 4; i++)
                ldsm4(af[i], aF + so + (uint32_t)(i * (16 * 80) + ks * 32));
#pragma unroll
            for (int j = 0; j < 4; j++)
                ldsm4(bfr[j], bF + so + (uint32_t)(j * (16 * 80) + ks * 32));
            if (isCorr) {
#pragma unroll
                for (int i = 0; i < 4; i++)
#pragma unroll
                    for (int j = 0; j < 4; j++) {
                        mma_f16acc(acc2[i][2 * j],     af[i], &bfr[j][0]);
                        mma_f16acc(acc2[i][2 * j + 1], af[i], &bfr[j][2]);
                    }
            } else {
#pragma unroll
                for (int i = 0; i < 4; i++)
#pragma unroll
                    for (int j = 0; j < 4; j++) {
                        mma_f32acc(acc[i][2 * j],     af[i], &bfr[j][0]);
                        mma_f32acc(acc[i][2 * j + 1], af[i], &bfr[j][2]);
                    }
            }
        }
    }

    // ---- epilogue ----
    const int gid = l >> 2, tig = l & 3;
#pragma unroll
    for (int i = 0; i < 4; i++) {
        const int r0g = blockM + wm * 64 + 16 * i + gid;
        const int r1g = r0g + 8;
        float um0 = 0.f, um1 = 0.f;
        if (EPI == 2 || EPI == 3) {
            um0 = uvec[(long)z * uStr + r0g];
            um1 = uvec[(long)z * uStr + r1g];
        }
        float part0 = 0.f, part1 = 0.f;
#pragma unroll
        for (int jj = 0; jj < 8; jj++) {
            const int c0 = blockN + wn * 64 + 8 * jj + 2 * tig;
            float x0 = acc[i][jj][0], x1 = acc[i][jj][1];
            float x2 = acc[i][jj][2], x3 = acc[i][jj][3];
            if (EPI == 0) {
                float* base = Cf + (long)z * sC;
                *(float2*)&base[(long)r0g * ldc + c0] = make_float2(x0, x1);
                *(float2*)&base[(long)r1g * ldc + c0] = make_float2(x2, x3);
            } else if (EPI == 2) {
                float2 vv = *(const float2*)&vvec[(long)z * vStr + c0];
                x0 += um0 + vv.x;  x1 += um0 + vv.y;
                x2 += um1 + vv.x;  x3 += um1 + vv.y;
                float* base = Cf + (long)z * sC;
                *(float2*)&base[(long)r0g * ldc + c0] = make_float2(x0, x1);
                *(float2*)&base[(long)r1g * ldc + c0] = make_float2(x2, x3);
            } else if (EPI == 1) {
                h16 h0 = __float2half_rn(x0), h1 = __float2half_rn(x1);
                h16 h2 = __float2half_rn(x2), h3 = __float2half_rn(x3);
                h16 l0 = __float2half_rn(x0 - __half2float(h0));
                h16 l1 = __float2half_rn(x1 - __half2float(h1));
                h16 l2 = __float2half_rn(x2 - __half2float(h2));
                h16 l3 = __float2half_rn(x3 - __half2float(h3));
                h16* bh = Chi + (long)z * sC;
                h16* bl = Clo + (long)z * sC;
                *(__half2*)&bh[(long)r0g * ldc + c0] = __halves2half2(h0, h1);
                *(__half2*)&bh[(long)r1g * ldc + c0] = __halves2half2(h2, h3);
                *(__half2*)&bl[(long)r0g * ldc + c0] = __halves2half2(l0, l1);
                *(__half2*)&bl[(long)r1g * ldc + c0] = __halves2half2(l2, l3);
            } else { // EPI == 3 : fused scorer on UNNORMALIZED att
                const float* rgB = regionF + (long)z * RR * DD;
                float2 w2 = *(const float2*)&WsP[DD + c0];
                float2 w3 = *(const float2*)&WsP[2 * DD + c0];
                float2 r0v = *(const float2*)&rgB[(long)r0g * DD + c0];
                float2 r1v = *(const float2*)&rgB[(long)r1g * DD + c0];
                part0 += x0 * (w2.x + r0v.x * w3.x) + x1 * (w2.y + r0v.y * w3.y);
                part1 += x2 * (w2.x + r1v.x * w3.x) + x3 * (w2.y + r1v.y * w3.y);
            }
        }
        if (EPI == 3) {
            part0 += __shfl_xor_sync(0xffffffffu, part0, 1);
            part0 += __shfl_xor_sync(0xffffffffu, part0, 2);
            part1 += __shfl_xor_sync(0xffffffffu, part1, 1);
            part1 += __shfl_xor_sync(0xffffffffu, part1, 2);
            if (tig == 0) {
                atomicAdd(&outP[(long)z * RR + r0g], part0 * um0);  // um = invden
                atomicAdd(&outP[(long)z * RR + r1g], part1 * um1);
            }
        }
    }
}

// ---------------------------------------------------------------------------
// Prep kernels (all fp16 splits now)
// ---------------------------------------------------------------------------
__global__ __launch_bounds__(256) void split_f16(
    const float* __restrict__ in, h16* __restrict__ h, h16* __restrict__ lo, long n4)
{
    long i = (long)blockIdx.x * blockDim.x + threadIdx.x;
    if (i >= n4) return;
    float4 v = ((const float4*)in)[i];
    h16 h0 = __float2half_rn(v.x), h1 = __float2half_rn(v.y);
    h16 h2 = __float2half_rn(v.z), h3 = __float2half_rn(v.w);
    h16 l0 = __float2half_rn(v.x - __half2float(h0));
    h16 l1 = __float2half_rn(v.y - __half2float(h1));
    h16 l2 = __float2half_rn(v.z - __half2float(h2));
    h16 l3 = __float2half_rn(v.w - __half2float(h3));
    ((__half2*)h )[2 * i]     = __halves2half2(h0, h1);
    ((__half2*)h )[2 * i + 1] = __halves2half2(h2, h3);
    ((__half2*)lo)[2 * i]     = __halves2half2(l0, l1);
    ((__half2*)lo)[2 * i + 1] = __halves2half2(l2, l3);
}

// sum 4 split-K fp32 partials -> fp16 hi/lo
__global__ __launch_bounds__(256) void reduce4_split(
    const float* __restrict__ part, h16* __restrict__ h, h16* __restrict__ lo, long n4)
{
    long i = (long)blockIdx.x * blockDim.x + threadIdx.x;
    if (i >= n4) return;
    float4 a = ((const float4*)part)[i];
    float4 b = ((const float4*)part)[i +     n4];
    float4 c = ((const float4*)part)[i + 2 * n4];
    float4 d = ((const float4*)part)[i + 3 * n4];
    float4 v = make_float4((a.x + b.x) + (c.x + d.x), (a.y + b.y) + (c.y + d.y),
                           (a.z + b.z) + (c.z + d.z), (a.w + b.w) + (c.w + d.w));
    h16 h0 = __float2half_rn(v.x), h1 = __float2half_rn(v.y);
    h16 h2 = __float2half_rn(v.z), h3 = __float2half_rn(v.w);
    h16 l0 = __float2half_rn(v.x - __half2float(h0));
    h16 l1 = __float2half_rn(v.y - __half2float(h1));
    h16 l2 = __float2half_rn(v.z - __half2float(h2));
    h16 l3 = __float2half_rn(v.w - __half2float(h3));
    ((__half2*)h )[2 * i]     = __halves2half2(h0, h1);
    ((__half2*)h )[2 * i + 1] = __halves2half2(h2, h3);
    ((__half2*)lo)[2 * i]     = __halves2half2(l0, l1);
    ((__half2*)lo)[2 * i + 1] = __halves2half2(l2, l3);
}

// fused: blocks 0-127 -> wrbq rows, 128-255 -> wqbr rows, block 256 -> c
__global__ __launch_bounds__(256) void weight_dots(
    const float* __restrict__ Wr, const float* __restrict__ Wq,
    const float* __restrict__ br, const float* __restrict__ bq,
    float* __restrict__ wrbq, float* __restrict__ wqbr, float* __restrict__ cptr)
{
    const int b = blockIdx.x;
    const int lane = threadIdx.x & 31, warp = threadIdx.x >> 5;
    if (b == 256) {
        if (warp == 0) {
            float s = 0.f;
            for (int k = lane; k < HH; k += 32) s += br[k] * bq[k];
#pragma unroll
            for (int o = 16; o > 0; o >>= 1) s += __shfl_xor_sync(0xffffffffu, s, o);
            if (lane == 0) cptr[0] = s;
        }
        return;
    }
    const float* X = (b < 128) ? Wr : Wq;
    const float* w = (b < 128) ? bq : br;
    float* outv    = (b < 128) ? wrbq : wqbr;
    const int row = (b & 127) * 8 + warp;
    const float* x = X + (long)row * HH;
    float s = 0.f;
    for (int k = lane; k < HH; k += 32) s += x[k] * w[k];
#pragma unroll
    for (int o = 16; o > 0; o >>= 1) s += __shfl_xor_sync(0xffffffffu, s, o);
    if (lane == 0) outv[row] = s;
}

__global__ __launch_bounds__(256) void prep_region(
    const float* __restrict__ region, const float* __restrict__ wrbq,
    const float* __restrict__ cptr, const float* __restrict__ Ws,
    const float* __restrict__ bs,
    h16* __restrict__ rh, h16* __restrict__ rl,
    float* __restrict__ u, float* __restrict__ outp)
{
    __shared__ float redA[8], redB[8];
    const long row = blockIdx.x;
    const int tid = threadIdx.x, lane = tid & 31, warp = tid >> 5;

    float4 v = ((const float4*)(region + row * DD))[tid];
    h16 h0 = __float2half_rn(v.x), h1 = __float2half_rn(v.y);
    h16 h2 = __float2half_rn(v.z), h3 = __float2half_rn(v.w);
    h16 l0 = __float2half_rn(v.x - __half2float(h0));
    h16 l1 = __float2half_rn(v.y - __half2float(h1));
    h16 l2 = __float2half_rn(v.z - __half2float(h2));
    h16 l3 = __float2half_rn(v.w - __half2float(h3));
    ((__half2*)(rh + row * DD))[2 * tid]     = __halves2half2(h0, h1);
    ((__half2*)(rh + row * DD))[2 * tid + 1] = __halves2half2(h2, h3);
    ((__half2*)(rl + row * DD))[2 * tid]     = __halves2half2(l0, l1);
    ((__half2*)(rl + row * DD))[2 * tid + 1] = __halves2half2(l2, l3);

    float4 w  = ((const float4*)wrbq)[tid];
    float4 w1 = ((const float4*)Ws  )[tid];
    float du = v.x * w.x  + v.y * w.y  + v.z * w.z  + v.w * w.w;
    float dn = v.x * w1.x + v.y * w1.y + v.z * w1.z + v.w * w1.w;
#pragma unroll
    for (int o = 16; o > 0; o >>= 1) {
        du += __shfl_xor_sync(0xffffffffu, du, o);
        dn += __shfl_xor_sync(0xffffffffu, dn, o);
    }
    if (lane == 0) { redA[warp] = du; redB[warp] = dn; }
    __syncthreads();
    if (tid == 0) {
        float su = 0.f, sn = 0.f;
#pragma unroll
        for (int k = 0; k < 8; k++) { su += redA[k]; sn += redB[k]; }
        u[row]    = su + cptr[0];
        outp[row] = sn + bs[0];
    }
}

__global__ __launch_bounds__(256) void prep_query(
    const float* __restrict__ query, const float* __restrict__ wqbr,
    h16* __restrict__ qh, h16* __restrict__ ql, float* __restrict__ vvec)
{
    __shared__ float red[8];
    const long row = blockIdx.x;
    const int tid = threadIdx.x, lane = tid & 31, warp = tid >> 5;

    float4 v = ((const float4*)(query + row * DD))[tid];
    h16 h0 = __float2half_rn(v.x), h1 = __float2half_rn(v.y);
    h16 h2 = __float2half_rn(v.z), h3 = __float2half_rn(v.w);
    h16 l0 = __float2half_rn(v.x - __half2float(h0));
    h16 l1 = __float2half_rn(v.y - __half2float(h1));
    h16 l2 = __float2half_rn(v.z - __half2float(h2));
    h16 l3 = __float2half_rn(v.w - __half2float(h3));
    ((__half2*)(qh + row * DD))[2 * tid]     = __halves2half2(h0, h1);
    ((__half2*)(qh + row * DD))[2 * tid + 1] = __halves2half2(h2, h3);
    ((__half2*)(ql + row * DD))[2 * tid]     = __halves2half2(l0, l1);
    ((__half2*)(ql + row * DD))[2 * tid + 1] = __halves2half2(l2, l3);

    float4 w = ((const float4*)wqbr)[tid];
    float d = v.x * w.x + v.y * w.y + v.z * w.z + v.w * w.w;
#pragma unroll
    for (int o = 16; o > 0; o >>= 1) d += __shfl_xor_sync(0xffffffffu, d, o);
    if (lane == 0) red[warp] = d;
    __syncthreads();
    if (tid == 0) {
        float s = 0.f;
#pragma unroll
        for (int k = 0; k < 8; k++) s += red[k];
        vvec[row] = s;
    }
}

__global__ __launch_bounds__(256) void transpose_split(
    const float* __restrict__ in, h16* __restrict__ oh, h16* __restrict__ ol)
{
    __shared__ float s[32][33];
    const float* ib = in + (long)blockIdx.z * TT * DD;
    h16* oh_b = oh + (long)blockIdx.z * DD * TT;
    h16* ol_b = ol + (long)blockIdx.z * DD * TT;
    const int d0 = blockIdx.x * 32, t0 = blockIdx.y * 32;
    const int tx = threadIdx.x, ty = threadIdx.y;
#pragma unroll
    for (int i = 0; i < 32; i += 8)
        s[ty + i][tx] = ib[(long)(t0 + ty + i) * DD + d0 + tx];
    __syncthreads();
#pragma unroll
    for (int i = 0; i < 32; i += 8) {
        float v = s[tx][ty + i];
        h16 h = __float2half_rn(v);
        long o = (long)(d0 + ty + i) * TT + t0 + tx;
        oh_b[o] = h;
        ol_b[o] = __float2half_rn(v - __half2float(h));
    }
}

// softmax numerator: exp(x - max) rounded to fp16; invden = 1/sum(rounded exp)
__global__ __launch_bounds__(128) void softmax_exp(
    const float* __restrict__ sc, h16* __restrict__ ae, float* __restrict__ invden)
{
    __shared__ float smax[4];
    __shared__ float ssum[4];
    const long row = blockIdx.x;
    const float4* p = (const float4*)(sc + row * TT);
    const int tid = threadIdx.x;
    const int lane = tid & 31, warp = tid >> 5;

    float4 v = p[tid];
    float m = fmaxf(fmaxf(v.x, v.y), fmaxf(v.z, v.w));
#pragma unroll
    for (int o = 16; o > 0; o >>= 1) m = fmaxf(m, __shfl_xor_sync(0xffffffffu, m, o));
    if (lane == 0) smax[warp] = m;
    __syncthreads();
    m = fmaxf(fmaxf(smax[0], smax[1]), fmaxf(smax[2], smax[3]));

    h16 e0 = __float2half_rn(expf(v.x - m));
    h16 e1 = __float2half_rn(expf(v.y - m));
    h16 e2 = __float2half_rn(expf(v.z - m));
    h16 e3 = __float2half_rn(expf(v.w - m));
    ((__half2*)(ae + row * TT))[2 * tid]     = __halves2half2(e0, e1);
    ((__half2*)(ae + row * TT))[2 * tid + 1] = __halves2half2(e2, e3);

    float s = __half2float(e0) + __half2float(e1)
            + __half2float(e2) + __half2float(e3);
#pragma unroll
    for (int o = 16; o > 0; o >>= 1) s += __shfl_xor_sync(0xffffffffu, s, o);
    if (lane == 0) ssum[warp] = s;
    __syncthreads();
    if (tid == 0)
        invden[row] = 1.0f / (ssum[0] + ssum[1] + ssum[2] + ssum[3]);
}

// ---------------------------------------------------------------------------
extern "C" void kernel_launch(void* const* d_in, const int* in_sizes, int n_in,
                              void* d_out, int out_size)
{
    (void)in_sizes; (void)n_in; (void)out_size;
    const float* region = (const float*)d_in[0];
    const float* query  = (const float*)d_in[1];
    const float* Wr     = (const float*)d_in[2];
    const float* br     = (const float*)d_in[3];
    const float* Wq     = (const float*)d_in[4];
    const float* bq     = (const float*)d_in[5];
    const float* Ws     = (const float*)d_in[6];
    const float* bs     = (const float*)d_in[7];
    float* out = (float*)d_out;

    h16 *region_h, *region_l, *query_h, *query_l;
    h16 *Wr_h, *Wr_l, *Wq_h, *Wq_l, *Mt_h, *Mt_l, *Qp_h, *Qp_l;
    h16 *qT_h, *qT_l, *attn_e;
    float *scores, *invden, *u, *v, *wrbq, *wqbr, *cptr;
    cudaGetSymbolAddress((void**)&region_h, g_region_h);
    cudaGetSymbolAddress((void**)&region_l, g_region_l);
    cudaGetSymbolAddress((void**)&query_h,  g_query_h);
    cudaGetSymbolAddress((void**)&query_l,  g_query_l);
    cudaGetSymbolAddress((void**)&Wr_h, g_Wr_h);
    cudaGetSymbolAddress((void**)&Wr_l, g_Wr_l);
    cudaGetSymbolAddress((void**)&Wq_h, g_Wq_h);
    cudaGetSymbolAddress((void**)&Wq_l, g_Wq_l);
    cudaGetSymbolAddress((void**)&Mt_h, g_Mt_h);
    cudaGetSymbolAddress((void**)&Mt_l, g_Mt_l);
    cudaGetSymbolAddress((void**)&Qp_h, g_Qp_h);
    cudaGetSymbolAddress((void**)&Qp_l, g_Qp_l);
    cudaGetSymbolAddress((void**)&qT_h, g_qT_h);
    cudaGetSymbolAddress((void**)&qT_l, g_qT_l);
    cudaGetSymbolAddress((void**)&attn_e, g_attn_e);
    cudaGetSymbolAddress((void**)&scores, g_scores);
    cudaGetSymbolAddress((void**)&invden, g_invden);
    cudaGetSymbolAddress((void**)&u,      g_u);
    cudaGetSymbolAddress((void**)&v,      g_v);
    cudaGetSymbolAddress((void**)&wrbq,   g_wrbq);
    cudaGetSymbolAddress((void**)&wqbr,   g_wqbr);
    cudaGetSymbolAddress((void**)&cptr,   g_c);

    float* Mt_part = scores;   // 4 x DD*DD fp32 partials (dead until step 3)

    cudaFuncSetAttribute((const void*)gemm3_f16<0,3>, cudaFuncAttributeMaxDynamicSharedMemorySize, SMEM_GEMM);
    cudaFuncSetAttribute((const void*)gemm3_f16<1,3>, cudaFuncAttributeMaxDynamicSharedMemorySize, SMEM_GEMM);
    cudaFuncSetAttribute((const void*)gemm3_f16<2,3>, cudaFuncAttributeMaxDynamicSharedMemorySize, SMEM_GEMM);
    cudaFuncSetAttribute((const void*)gemm3_f16<3,2>, cudaFuncAttributeMaxDynamicSharedMemorySize, SMEM_GEMM);

    // weight prep
    split_f16<<<(unsigned)(((long)DD*HH/4 + 255)/256), 256>>>(Wr, Wr_h, Wr_l, (long)DD*HH/4);
    split_f16<<<(unsigned)(((long)DD*HH/4 + 255)/256), 256>>>(Wq, Wq_h, Wq_l, (long)DD*HH/4);
    weight_dots<<<257, 256>>>(Wr, Wq, br, bq, wrbq, wqbr, cptr);

    // fused input prep
    prep_query <<<BB*TT, 256>>>(query, wqbr, query_h, query_l, v);
    prep_region<<<BB*RR, 256>>>(region, wrbq, cptr, Ws, bs, region_h, region_l, u, out);
    transpose_split<<<dim3(DD/32, TT/32, BB), dim3(32, 8)>>>(query, qT_h, qT_l);

    // 1) Mt2 = Wr @ Wq^T  (fp16x3, split-K x4 -> private fp32 partials, then reduce+split)
    gemm3_f16<0,3><<<dim3(8, 8, 4), 128, SMEM_GEMM>>>(
        Wr_h, Wr_l, Wq_h, Wq_l, Mt_part, nullptr, nullptr, nullptr, nullptr,
        nullptr, nullptr, nullptr,
        /*Kbase=*/HH/4, /*lda=*/HH, /*ldb=*/HH, /*ldc=*/DD,
        /*sA=*/HH/4, /*sB=*/HH/4, /*sC=*/(long)DD*DD, 0, 0);
    reduce4_split<<<(unsigned)(((long)DD*DD/4 + 255)/256), 256>>>(
        Mt_part, Mt_h, Mt_l, (long)DD*DD/4);

    // 2) Qp[b] = query[b] @ Mt2^T  (fp16x3, split out)
    gemm3_f16<1,3><<<dim3(8, 4, BB), 128, SMEM_GEMM>>>(
        query_h, query_l, Mt_h, Mt_l, nullptr, Qp_h, Qp_l, nullptr, nullptr,
        nullptr, nullptr, nullptr,
        DD, DD, DD, DD, (long)TT*DD, 0, (long)TT*DD, 0, 0);

    // 3) scores[b] = region[b] @ Qp[b]^T + u + v  (fp16x3)
    gemm3_f16<2,3><<<dim3(4, 8, BB), 128, SMEM_GEMM>>>(
        region_h, region_l, Qp_h, Qp_l, scores, nullptr, nullptr, u, v,
        nullptr, nullptr, nullptr,
        DD, DD, DD, TT, (long)RR*DD, (long)TT*DD, (long)RR*TT, RR, TT);

    // 4) softmax numerator -> fp16 exp + invden
    softmax_exp<<<BB*RR, 128>>>(scores, attn_e, invden);

    // 5) attU[b] @ queryT[b]^T  (2-phase), fused scorer epilogue
    gemm3_f16<3,2><<<dim3(8, 8, BB), 128, SMEM_GEMM>>>(
        attn_e, attn_e, qT_h, qT_l, nullptr, nullptr, nullptr, invden, nullptr,
        region, Ws, out,
        TT, TT, TT, DD, (long)RR*TT, (long)DD*TT, 0, RR, 0);
}

// round 14
// speedup vs baseline: 1.9902x; 1.9902x over previous
#include <cuda_runtime.h>
#include <cuda_fp16.h>
#include <cstdint>

#define BB 16
#define RR 1024
#define TT 512
#define DD 1024
#define HH 1024

typedef __half h16;

// ---------------------------------------------------------------------------
// Scratch (__device__ globals; allocation-free rule)
// ---------------------------------------------------------------------------
__device__ h16 g_region_h[BB*RR*DD], g_region_l[BB*RR*DD];
__device__ h16 g_query_h [BB*TT*DD], g_query_l [BB*TT*DD];
__device__ h16 g_Wr_h[DD*HH], g_Wr_l[DD*HH];
__device__ h16 g_Wq_h[DD*HH], g_Wq_l[DD*HH];
__device__ h16 g_Mt_h[DD*DD], g_Mt_l[DD*DD];        // Mt2 = Wr @ Wq^T
__device__ h16 g_Qp_h[BB*TT*DD], g_Qp_l[BB*TT*DD];  // Qp = query @ Mt2^T
__device__ h16 g_qT_h[BB*DD*TT], g_qT_l[BB*DD*TT];  // query^T [B][D][T]
__device__ h16 g_attn_e[BB*RR*TT];                  // unnormalized exp (fp16)
__device__ float g_scores[BB*RR*TT];                // ALSO reused: first 4*DD*DD floats = Mt split-K partials
__device__ float g_invden[BB*RR];
__device__ float g_u[BB*RR];
__device__ float g_v[BB*TT];
__device__ float g_wrbq[DD];
__device__ float g_wqbr[DD];
__device__ float g_c[1];

// ---------------------------------------------------------------------------
// PTX helpers (sm_80-compatible; compiles for compute_103 virtual arch)
// ---------------------------------------------------------------------------
__device__ __forceinline__ uint32_t smem_u32(const void* p) {
    uint32_t a;
    asm("{ .reg .u64 t; cvta.to.shared.u64 t, %1; cvt.u32.u64 %0, t; }" : "=r"(a) : "l"(p));
    return a;
}
#define CP_ASYNC16(dst, src) \
    asm volatile("cp.async.cg.shared.global [%0], [%1], 16;" :: "r"(dst), "l"(src))
#define CP_COMMIT() asm volatile("cp.async.commit_group;" ::: "memory")
#define CP_WAIT2()  asm volatile("cp.async.wait_group 2;" ::: "memory")
#define CP_WAIT1()  asm volatile("cp.async.wait_group 1;" ::: "memory")
#define CP_WAIT0()  asm volatile("cp.async.wait_group 0;" ::: "memory")

__device__ __forceinline__ void ldsm4(uint32_t* r, uint32_t addr) {
    asm volatile("ldmatrix.sync.aligned.m8n8.x4.shared.b16 {%0,%1,%2,%3}, [%4];"
                 : "=r"(r[0]), "=r"(r[1]), "=r"(r[2]), "=r"(r[3]) : "r"(addr));
}
// fp16 inputs, f32 accumulate (ONLY mma used — single accumulator bank)
__device__ __forceinline__ void mma16816(float* d, const uint32_t* a, const uint32_t* b) {
    asm volatile("mma.sync.aligned.m16n8k16.row.col.f32.f16.f16.f32 "
                 "{%0,%1,%2,%3}, {%4,%5,%6,%7}, {%8,%9}, {%0,%1,%2,%3};"
                 : "+f"(d[0]), "+f"(d[1]), "+f"(d[2]), "+f"(d[3])
                 : "r"(a[0]), "r"(a[1]), "r"(a[2]), "r"(a[3]), "r"(b[0]), "r"(b[1]));
}

// ---------------------------------------------------------------------------
// fp16 multi-phase GEMM (NT), all f32-accumulate:
//   NPH=3: phases { Ah*Bh, Ah*Bl, Al*Bh }
//   NPH=2: phases { Ah*Bh, Ah*Bl }   (A split unused / Al ignored)
// Block 128x128, BK=32, 4 warps (64x64 warp tile), 4-stage cp.async.
// EPI: 0 = plain fp32 store to Cf + z*sC (split-K partials; z also offsets A/B);
//      1 = fp16 hi/lo split store; 2 = fp32 + u[m] + v[n];
//      3 = fused scorer: atomicAdd out[r] += invden[r]*sum_c C*(Ws2+region*Ws3)
// ---------------------------------------------------------------------------
#define STAGE_B 20480
#define NSTAGE  4
#define SMEM_GEMM (NSTAGE * STAGE_B)   // 80 KB dynamic

template <int EPI, int NPH>
__global__ __launch_bounds__(128, 2) void gemm3_f16(
    const h16* __restrict__ Ah, const h16* __restrict__ Al,
    const h16* __restrict__ Bh, const h16* __restrict__ Bl,
    float* __restrict__ Cf, h16* __restrict__ Chi, h16* __restrict__ Clo,
    const float* __restrict__ uvec, const float* __restrict__ vvec,
    const float* __restrict__ regionF, const float* __restrict__ WsP,
    float* __restrict__ outP,
    int Kbase, int lda, int ldb, int ldc,
    long sA, long sB, long sC, int uStr, int vStr)
{
    extern __shared__ __align__(16) uint8_t smem_raw[];
    const int tid = threadIdx.x;
    const int wid = tid >> 5, l = tid & 31;
    const int wm = wid >> 1, wn = wid & 1;
    const int blockM = blockIdx.y * 128, blockN = blockIdx.x * 128;
    const int z = blockIdx.z;

    Ah += (long)z * sA;  Al += (long)z * sA;
    Bh += (long)z * sB;  Bl += (long)z * sB;

    const uint32_t smBase = smem_u32(smem_raw);
    const int cpb = Kbase / 32;
    const int NK  = NPH * cpb;

    const uint32_t aF = smBase +
        (uint32_t)((wm * 64 + (l & 15)) * 80 + ((l >> 4) * 16));
    const int bn = (l & 7) + ((l & 16) >> 1);
    const uint32_t bF = smBase + 10240u +
        (uint32_t)((wn * 64 + bn) * 80 + (((l >> 3) & 1) * 16));

    float acc[4][8][4];
#pragma unroll
    for (int i = 0; i < 4; i++)
#pragma unroll
        for (int j = 0; j < 8; j++)
#pragma unroll
            for (int q = 0; q < 4; q++) acc[i][j][q] = 0.f;

    const int lr = tid >> 2, lj = tid & 3;

    auto load_stage = [&](int stage, int kb) {
        const int ph  = kb / cpb;
        const int kbl = kb - ph * cpb;
        const h16* Ap = (NPH == 3 && ph == 2) ? Al : Ah;
        const h16* Bp = (ph == 1) ? Bl : Bh;
        const int k0 = kbl * 32;
        const uint32_t sa = smBase + stage * STAGE_B;
        const uint32_t sb = sa + 10240u;
#pragma unroll
        for (int it = 0; it < 4; it++) {
            const int rr = lr + it * 32;
            const h16* ga = Ap + (long)(blockM + rr) * lda + k0 + lj * 8;
            CP_ASYNC16(sa + (uint32_t)(rr * 80 + lj * 16), ga);
            const h16* gb = Bp + (long)(blockN + rr) * ldb + k0 + lj * 8;
            CP_ASYNC16(sb + (uint32_t)(rr * 80 + lj * 16), gb);
        }
        CP_COMMIT();
    };

    load_stage(0, 0);
    load_stage(1, 1);
    load_stage(2, 2);

    for (int kb = 0; kb < NK; kb++) {
        if (kb < NK - 2)       CP_WAIT2();
        else if (kb == NK - 2) CP_WAIT1();
        else                   CP_WAIT0();
        __syncthreads();
        if (kb + 3 < NK) load_stage((kb + 3) & 3, kb + 3);

        const uint32_t so = (uint32_t)(kb & 3) * STAGE_B;
#pragma unroll
        for (int ks = 0; ks < 2; ks++) {
            uint32_t af[4][4], bfr[4][4];
#pragma unroll
            for (int i = 0; i < 4; i++)
                ldsm4(af[i], aF + so + (uint32_t)(i * (16 * 80) + ks * 32));
#pragma unroll
            for (int j = 0; j < 4; j++)
                ldsm4(bfr[j], bF + so + (uint32_t)(j * (16 * 80) + ks * 32));
#pragma unroll
            for (int i = 0; i < 4; i++)
#pragma unroll
                for (int j = 0; j < 4; j++) {
                    mma16816(acc[i][2 * j],     af[i], &bfr[j][0]);
                    mma16816(acc[i][2 * j + 1], af[i], &bfr[j][2]);
                }
        }
    }

    // ---- epilogue ----
    const int gid = l >> 2, tig = l & 3;
#pragma unroll
    for (int i = 0; i < 4; i++) {
        const int r0g = blockM + wm * 64 + 16 * i + gid;
        const int r1g = r0g + 8;
        float um0 = 0.f, um1 = 0.f;
        if (EPI == 2 || EPI == 3) {
            um0 = uvec[(long)z * uStr + r0g];
            um1 = uvec[(long)z * uStr + r1g];
        }
        float part0 = 0.f, part1 = 0.f;
#pragma unroll
        for (int jj = 0; jj < 8; jj++) {
            const int c0 = blockN + wn * 64 + 8 * jj + 2 * tig;
            float x0 = acc[i][jj][0], x1 = acc[i][jj][1];
            float x2 = acc[i][jj][2], x3 = acc[i][jj][3];
            if (EPI == 0) {
                float* base = Cf + (long)z * sC;
                *(float2*)&base[(long)r0g * ldc + c0] = make_float2(x0, x1);
                *(float2*)&base[(long)r1g * ldc + c0] = make_float2(x2, x3);
            } else if (EPI == 2) {
                float2 vv = *(const float2*)&vvec[(long)z * vStr + c0];
                x0 += um0 + vv.x;  x1 += um0 + vv.y;
                x2 += um1 + vv.x;  x3 += um1 + vv.y;
                float* base = Cf + (long)z * sC;
                *(float2*)&base[(long)r0g * ldc + c0] = make_float2(x0, x1);
                *(float2*)&base[(long)r1g * ldc + c0] = make_float2(x2, x3);
            } else if (EPI == 1) {
                h16 h0 = __float2half_rn(x0), h1 = __float2half_rn(x1);
                h16 h2 = __float2half_rn(x2), h3 = __float2half_rn(x3);
                h16 l0 = __float2half_rn(x0 - __half2float(h0));
                h16 l1 = __float2half_rn(x1 - __half2float(h1));
                h16 l2 = __float2half_rn(x2 - __half2float(h2));
                h16 l3 = __float2half_rn(x3 - __half2float(h3));
                h16* bh = Chi + (long)z * sC;
                h16* bl = Clo + (long)z * sC;
                *(__half2*)&bh[(long)r0g * ldc + c0] = __halves2half2(h0, h1);
                *(__half2*)&bh[(long)r1g * ldc + c0] = __halves2half2(h2, h3);
                *(__half2*)&bl[(long)r0g * ldc + c0] = __halves2half2(l0, l1);
                *(__half2*)&bl[(long)r1g * ldc + c0] = __halves2half2(l2, l3);
            } else { // EPI == 3 : fused scorer on UNNORMALIZED att
                const float* rgB = regionF + (long)z * RR * DD;
                float2 w2 = *(const float2*)&WsP[DD + c0];
                float2 w3 = *(const float2*)&WsP[2 * DD + c0];
                float2 r0v = *(const float2*)&rgB[(long)r0g * DD + c0];
                float2 r1v = *(const float2*)&rgB[(long)r1g * DD + c0];
                part0 += x0 * (w2.x + r0v.x * w3.x) + x1 * (w2.y + r0v.y * w3.y);
                part1 += x2 * (w2.x + r1v.x * w3.x) + x3 * (w2.y + r1v.y * w3.y);
            }
        }
        if (EPI == 3) {
            part0 += __shfl_xor_sync(0xffffffffu, part0, 1);
            part0 += __shfl_xor_sync(0xffffffffu, part0, 2);
            part1 += __shfl_xor_sync(0xffffffffu, part1, 1);
            part1 += __shfl_xor_sync(0xffffffffu, part1, 2);
            if (tig == 0) {
                atomicAdd(&outP[(long)z * RR + r0g], part0 * um0);  // um = invden
                atomicAdd(&outP[(long)z * RR + r1g], part1 * um1);
            }
        }
    }
}

// ---------------------------------------------------------------------------
// Prep kernels (fp16 splits)
// ---------------------------------------------------------------------------
__global__ __launch_bounds__(256) void split_f16(
    const float* __restrict__ in, h16* __restrict__ h, h16* __restrict__ lo, long n4)
{
    long i = (long)blockIdx.x * blockDim.x + threadIdx.x;
    if (i >= n4) return;
    float4 v = ((const float4*)in)[i];
    h16 h0 = __float2half_rn(v.x), h1 = __float2half_rn(v.y);
    h16 h2 = __float2half_rn(v.z), h3 = __float2half_rn(v.w);
    h16 l0 = __float2half_rn(v.x - __half2float(h0));
    h16 l1 = __float2half_rn(v.y - __half2float(h1));
    h16 l2 = __float2half_rn(v.z - __half2float(h2));
    h16 l3 = __float2half_rn(v.w - __half2float(h3));
    ((__half2*)h )[2 * i]     = __halves2half2(h0, h1);
    ((__half2*)h )[2 * i + 1] = __halves2half2(h2, h3);
    ((__half2*)lo)[2 * i]     = __halves2half2(l0, l1);
    ((__half2*)lo)[2 * i + 1] = __halves2half2(l2, l3);
}

// sum 4 split-K fp32 partials -> fp16 hi/lo
__global__ __launch_bounds__(256) void reduce4_split(
    const float* __restrict__ part, h16* __restrict__ h, h16* __restrict__ lo, long n4)
{
    long i = (long)blockIdx.x * blockDim.x + threadIdx.x;
    if (i >= n4) return;
    float4 a = ((const float4*)part)[i];
    float4 b = ((const float4*)part)[i +     n4];
    float4 c = ((const float4*)part)[i + 2 * n4];
    float4 d = ((const float4*)part)[i + 3 * n4];
    float4 v = make_float4((a.x + b.x) + (c.x + d.x), (a.y + b.y) + (c.y + d.y),
                           (a.z + b.z) + (c.z + d.z), (a.w + b.w) + (c.w + d.w));
    h16 h0 = __float2half_rn(v.x), h1 = __float2half_rn(v.y);
    h16 h2 = __float2half_rn(v.z), h3 = __float2half_rn(v.w);
    h16 l0 = __float2half_rn(v.x - __half2float(h0));
    h16 l1 = __float2half_rn(v.y - __half2float(h1));
    h16 l2 = __float2half_rn(v.z - __half2float(h2));
    h16 l3 = __float2half_rn(v.w - __half2float(h3));
    ((__half2*)h )[2 * i]     = __halves2half2(h0, h1);
    ((__half2*)h )[2 * i + 1] = __halves2half2(h2, h3);
    ((__half2*)lo)[2 * i]     = __halves2half2(l0, l1);
    ((__half2*)lo)[2 * i + 1] = __halves2half2(l2, l3);
}

// fused: blocks 0-127 -> wrbq rows, 128-255 -> wqbr rows, block 256 -> c
__global__ __launch_bounds__(256) void weight_dots(
    const float* __restrict__ Wr, const float* __restrict__ Wq,
    const float* __restrict__ br, const float* __restrict__ bq,
    float* __restrict__ wrbq, float* __restrict__ wqbr, float* __restrict__ cptr)
{
    const int b = blockIdx.x;
    const int lane = threadIdx.x & 31, warp = threadIdx.x >> 5;
    if (b == 256) {
        if (warp == 0) {
            float s = 0.f;
            for (int k = lane; k < HH; k += 32) s += br[k] * bq[k];
#pragma unroll
            for (int o = 16; o > 0; o >>= 1) s += __shfl_xor_sync(0xffffffffu, s, o);
            if (lane == 0) cptr[0] = s;
        }
        return;
    }
    const float* X = (b < 128) ? Wr : Wq;
    const float* w = (b < 128) ? bq : br;
    float* outv    = (b < 128) ? wrbq : wqbr;
    const int row = (b & 127) * 8 + warp;
    const float* x = X + (long)row * HH;
    float s = 0.f;
    for (int k = lane; k < HH; k += 32) s += x[k] * w[k];
#pragma unroll
    for (int o = 16; o > 0; o >>= 1) s += __shfl_xor_sync(0xffffffffu, s, o);
    if (lane == 0) outv[row] = s;
}

__global__ __launch_bounds__(256) void prep_region(
    const float* __restrict__ region, const float* __restrict__ wrbq,
    const float* __restrict__ cptr, const float* __restrict__ Ws,
    const float* __restrict__ bs,
    h16* __restrict__ rh, h16* __restrict__ rl,
    float* __restrict__ u, float* __restrict__ outp)
{
    __shared__ float redA[8], redB[8];
    const long row = blockIdx.x;
    const int tid = threadIdx.x, lane = tid & 31, warp = tid >> 5;

    float4 v = ((const float4*)(region + row * DD))[tid];
    h16 h0 = __float2half_rn(v.x), h1 = __float2half_rn(v.y);
    h16 h2 = __float2half_rn(v.z), h3 = __float2half_rn(v.w);
    h16 l0 = __float2half_rn(v.x - __half2float(h0));
    h16 l1 = __float2half_rn(v.y - __half2float(h1));
    h16 l2 = __float2half_rn(v.z - __half2float(h2));
    h16 l3 = __float2half_rn(v.w - __half2float(h3));
    ((__half2*)(rh + row * DD))[2 * tid]     = __halves2half2(h0, h1);
    ((__half2*)(rh + row * DD))[2 * tid + 1] = __halves2half2(h2, h3);
    ((__half2*)(rl + row * DD))[2 * tid]     = __halves2half2(l0, l1);
    ((__half2*)(rl + row * DD))[2 * tid + 1] = __halves2half2(l2, l3);

    float4 w  = ((const float4*)wrbq)[tid];
    float4 w1 = ((const float4*)Ws  )[tid];
    float du = v.x * w.x  + v.y * w.y  + v.z * w.z  + v.w * w.w;
    float dn = v.x * w1.x + v.y * w1.y + v.z * w1.z + v.w * w1.w;
#pragma unroll
    for (int o = 16; o > 0; o >>= 1) {
        du += __shfl_xor_sync(0xffffffffu, du, o);
        dn += __shfl_xor_sync(0xffffffffu, dn, o);
    }
    if (lane == 0) { redA[warp] = du; redB[warp] = dn; }
    __syncthreads();
    if (tid == 0) {
        float su = 0.f, sn = 0.f;
#pragma unroll
        for (int k = 0; k < 8; k++) { su += redA[k]; sn += redB[k]; }
        u[row]    = su + cptr[0];
        outp[row] = sn + bs[0];
    }
}

__global__ __launch_bounds__(256) void prep_query(
    const float* __restrict__ query, const float* __restrict__ wqbr,
    h16* __restrict__ qh, h16* __restrict__ ql, float* __restrict__ vvec)
{
    __shared__ float red[8];
    const long row = blockIdx.x;
    const int tid = threadIdx.x, lane = tid & 31, warp = tid >> 5;

    float4 v = ((const float4*)(query + row * DD))[tid];
    h16 h0 = __float2half_rn(v.x), h1 = __float2half_rn(v.y);
    h16 h2 = __float2half_rn(v.z), h3 = __float2half_rn(v.w);
    h16 l0 = __float2half_rn(v.x - __half2float(h0));
    h16 l1 = __float2half_rn(v.y - __half2float(h1));
    h16 l2 = __float2half_rn(v.z - __half2float(h2));
    h16 l3 = __float2half_rn(v.w - __half2float(h3));
    ((__half2*)(qh + row * DD))[2 * tid]     = __halves2half2(h0, h1);
    ((__half2*)(qh + row * DD))[2 * tid + 1] = __halves2half2(h2, h3);
    ((__half2*)(ql + row * DD))[2 * tid]     = __halves2half2(l0, l1);
    ((__half2*)(ql + row * DD))[2 * tid + 1] = __halves2half2(l2, l3);

    float4 w = ((const float4*)wqbr)[tid];
    float d = v.x * w.x + v.y * w.y + v.z * w.z + v.w * w.w;
#pragma unroll
    for (int o = 16; o > 0; o >>= 1) d += __shfl_xor_sync(0xffffffffu, d, o);
    if (lane == 0) red[warp] = d;
    __syncthreads();
    if (tid == 0) {
        float s = 0.f;
#pragma unroll
        for (int k = 0; k < 8; k++) s += red[k];
        vvec[row] = s;
    }
}

__global__ __launch_bounds__(256) void transpose_split(
    const float* __restrict__ in, h16* __restrict__ oh, h16* __restrict__ ol)
{
    __shared__ float s[32][33];
    const float* ib = in + (long)blockIdx.z * TT * DD;
    h16* oh_b = oh + (long)blockIdx.z * DD * TT;
    h16* ol_b = ol + (long)blockIdx.z * DD * TT;
    const int d0 = blockIdx.x * 32, t0 = blockIdx.y * 32;
    const int tx = threadIdx.x, ty = threadIdx.y;
#pragma unroll
    for (int i = 0; i < 32; i += 8)
        s[ty + i][tx] = ib[(long)(t0 + ty + i) * DD + d0 + tx];
    __syncthreads();
#pragma unroll
    for (int i = 0; i < 32; i += 8) {
        float v = s[tx][ty + i];
        h16 h = __float2half_rn(v);
        long o = (long)(d0 + ty + i) * TT + t0 + tx;
        oh_b[o] = h;
        ol_b[o] = __float2half_rn(v - __half2float(h));
    }
}

// softmax numerator: exp(x - max) rounded to fp16; invden = 1/sum(rounded exp)
__global__ __launch_bounds__(128) void softmax_exp(
    const float* __restrict__ sc, h16* __restrict__ ae, float* __restrict__ invden)
{
    __shared__ float smax[4];
    __shared__ float ssum[4];
    const long row = blockIdx.x;
    const float4* p = (const float4*)(sc + row * TT);
    const int tid = threadIdx.x;
    const int lane = tid & 31, warp = tid >> 5;

    float4 v = p[tid];
    float m = fmaxf(fmaxf(v.x, v.y), fmaxf(v.z, v.w));
#pragma unroll
    for (int o = 16; o > 0; o >>= 1) m = fmaxf(m, __shfl_xor_sync(0xffffffffu, m, o));
    if (lane == 0) smax[warp] = m;
    __syncthreads();
    m = fmaxf(fmaxf(smax[0], smax[1]), fmaxf(smax[2], smax[3]));

    h16 e0 = __float2half_rn(expf(v.x - m));
    h16 e1 = __float2half_rn(expf(v.y - m));
    h16 e2 = __float2half_rn(expf(v.z - m));
    h16 e3 = __float2half_rn(expf(v.w - m));
    ((__half2*)(ae + row * TT))[2 * tid]     = __halves2half2(e0, e1);
    ((__half2*)(ae + row * TT))[2 * tid + 1] = __halves2half2(e2, e3);

    float s = __half2float(e0) + __half2float(e1)
            + __half2float(e2) + __half2float(e3);
#pragma unroll
    for (int o = 16; o > 0; o >>= 1) s += __shfl_xor_sync(0xffffffffu, s, o);
    if (lane == 0) ssum[warp] = s;
    __syncthreads();
    if (tid == 0)
        invden[row] = 1.0f / (ssum[0] + ssum[1] + ssum[2] + ssum[3]);
}

// ---------------------------------------------------------------------------
extern "C" void kernel_launch(void* const* d_in, const int* in_sizes, int n_in,
                              void* d_out, int out_size)
{
    (void)in_sizes; (void)n_in; (void)out_size;
    const float* region = (const float*)d_in[0];
    const float* query  = (const float*)d_in[1];
    const float* Wr     = (const float*)d_in[2];
    const float* br     = (const float*)d_in[3];
    const float* Wq     = (const float*)d_in[4];
    const float* bq     = (const float*)d_in[5];
    const float* Ws     = (const float*)d_in[6];
    const float* bs     = (const float*)d_in[7];
    float* out = (float*)d_out;

    h16 *region_h, *region_l, *query_h, *query_l;
    h16 *Wr_h, *Wr_l, *Wq_h, *Wq_l, *Mt_h, *Mt_l, *Qp_h, *Qp_l;
    h16 *qT_h, *qT_l, *attn_e;
    float *scores, *invden, *u, *v, *wrbq, *wqbr, *cptr;
    cudaGetSymbolAddress((void**)&region_h, g_region_h);
    cudaGetSymbolAddress((void**)&region_l, g_region_l);
    cudaGetSymbolAddress((void**)&query_h,  g_query_h);
    cudaGetSymbolAddress((void**)&query_l,  g_query_l);
    cudaGetSymbolAddress((void**)&Wr_h, g_Wr_h);
    cudaGetSymbolAddress((void**)&Wr_l, g_Wr_l);
    cudaGetSymbolAddress((void**)&Wq_h, g_Wq_h);
    cudaGetSymbolAddress((void**)&Wq_l, g_Wq_l);
    cudaGetSymbolAddress((void**)&Mt_h, g_Mt_h);
    cudaGetSymbolAddress((void**)&Mt_l, g_Mt_l);
    cudaGetSymbolAddress((void**)&Qp_h, g_Qp_h);
    cudaGetSymbolAddress((void**)&Qp_l, g_Qp_l);
    cudaGetSymbolAddress((void**)&qT_h, g_qT_h);
    cudaGetSymbolAddress((void**)&qT_l, g_qT_l);
    cudaGetSymbolAddress((void**)&attn_e, g_attn_e);
    cudaGetSymbolAddress((void**)&scores, g_scores);
    cudaGetSymbolAddress((void**)&invden, g_invden);
    cudaGetSymbolAddress((void**)&u,      g_u);
    cudaGetSymbolAddress((void**)&v,      g_v);
    cudaGetSymbolAddress((void**)&wrbq,   g_wrbq);
    cudaGetSymbolAddress((void**)&wqbr,   g_wqbr);
    cudaGetSymbolAddress((void**)&cptr,   g_c);

    float* Mt_part = scores;   // 4 x DD*DD fp32 partials (dead until step 3)

    cudaFuncSetAttribute((const void*)gemm3_f16<0,3>, cudaFuncAttributeMaxDynamicSharedMemorySize, SMEM_GEMM);
    cudaFuncSetAttribute((const void*)gemm3_f16<1,3>, cudaFuncAttributeMaxDynamicSharedMemorySize, SMEM_GEMM);
    cudaFuncSetAttribute((const void*)gemm3_f16<2,2>, cudaFuncAttributeMaxDynamicSharedMemorySize, SMEM_GEMM);
    cudaFuncSetAttribute((const void*)gemm3_f16<3,2>, cudaFuncAttributeMaxDynamicSharedMemorySize, SMEM_GEMM);

    // weight prep
    split_f16<<<(unsigned)(((long)DD*HH/4 + 255)/256), 256>>>(Wr, Wr_h, Wr_l, (long)DD*HH/4);
    split_f16<<<(unsigned)(((long)DD*HH/4 + 255)/256), 256>>>(Wq, Wq_h, Wq_l, (long)DD*HH/4);
    weight_dots<<<257, 256>>>(Wr, Wq, br, bq, wrbq, wqbr, cptr);

    // fused input prep
    prep_query <<<BB*TT, 256>>>(query, wqbr, query_h, query_l, v);
    prep_region<<<BB*RR, 256>>>(region, wrbq, cptr, Ws, bs, region_h, region_l, u, out);
    transpose_split<<<dim3(DD/32, TT/32, BB), dim3(32, 8)>>>(query, qT_h, qT_l);

    // 1) Mt2 = Wr @ Wq^T  (fp16x3, split-K x4 -> private fp32 partials, then reduce+split)
    gemm3_f16<0,3><<<dim3(8, 8, 4), 128, SMEM_GEMM>>>(
        Wr_h, Wr_l, Wq_h, Wq_l, Mt_part, nullptr, nullptr, nullptr, nullptr,
        nullptr, nullptr, nullptr,
        /*Kbase=*/HH/4, /*lda=*/HH, /*ldb=*/HH, /*ldc=*/DD,
        /*sA=*/HH/4, /*sB=*/HH/4, /*sC=*/(long)DD*DD, 0, 0);
    reduce4_split<<<(unsigned)(((long)DD*DD/4 + 255)/256), 256>>>(
        Mt_part, Mt_h, Mt_l, (long)DD*DD/4);

    // 2) Qp[b] = query[b] @ Mt2^T  (fp16x3, split out)
    gemm3_f16<1,3><<<dim3(8, 4, BB), 128, SMEM_GEMM>>>(
        query_h, query_l, Mt_h, Mt_l, nullptr, Qp_h, Qp_l, nullptr, nullptr,
        nullptr, nullptr, nullptr,
        DD, DD, DD, DD, (long)TT*DD, 0, (long)TT*DD, 0, 0);

    // 3) scores[b] = region[b] @ Qp[b]^T + u + v  (fp16x2: region_h * {Qp_h, Qp_l})
    gemm3_f16<2,2><<<dim3(4, 8, BB), 128, SMEM_GEMM>>>(
        region_h, region_h, Qp_h, Qp_l, scores, nullptr, nullptr, u, v,
        nullptr, nullptr, nullptr,
        DD, DD, DD, TT, (long)RR*DD, (long)TT*DD, (long)RR*TT, RR, TT);

    // 4) softmax numerator -> fp16 exp + invden
    softmax_exp<<<BB*RR, 128>>>(scores, attn_e, invden);

    // 5) attU[b] @ queryT[b]^T  (fp16x2), fused scorer epilogue
    gemm3_f16<3,2><<<dim3(8, 8, BB), 128, SMEM_GEMM>>>(
        attn_e, attn_e, qT_h, qT_l, nullptr, nullptr, nullptr, invden, nullptr,
        region, Ws, out,
        TT, TT, TT, DD, (long)RR*TT, (long)DD*TT, 0, RR, 0);
}

// round 15
// speedup vs baseline: 1.9941x; 1.0020x over previous
#include <cuda_runtime.h>
#include <cuda_fp16.h>
#include <cstdint>

#define BB 16
#define RR 1024
#define TT 512
#define DD 1024
#define HH 1024

typedef __half h16;

// ---------------------------------------------------------------------------
// Scratch (__device__ globals; allocation-free rule)
// ---------------------------------------------------------------------------
__device__ h16 g_region_h[BB*RR*DD], g_region_l[BB*RR*DD];
__device__ h16 g_query_h [BB*TT*DD], g_query_l [BB*TT*DD];
__device__ h16 g_Wr_h[DD*HH], g_Wr_l[DD*HH];
__device__ h16 g_Wq_h[DD*HH], g_Wq_l[DD*HH];
__device__ h16 g_Mt_h[DD*DD], g_Mt_l[DD*DD];        // Mt2 = Wr @ Wq^T
__device__ h16 g_Qp_h[BB*TT*DD], g_Qp_l[BB*TT*DD];  // Qp = query @ Mt2^T
__device__ h16 g_qT_h[BB*DD*TT];                    // query^T [B][D][T] (hi only)
__device__ h16 g_attn_e[BB*RR*TT];                  // unnormalized exp (fp16)
__device__ float g_scores[BB*RR*TT];                // ALSO reused: first 4*DD*DD floats = Mt split-K partials
__device__ float g_invden[BB*RR];
__device__ float g_u[BB*RR];
__device__ float g_v[BB*TT];
__device__ float g_wrbq[DD];
__device__ float g_wqbr[DD];
__device__ float g_c[1];

// ---------------------------------------------------------------------------
// PTX helpers (sm_80-compatible; compiles for compute_103 virtual arch)
// ---------------------------------------------------------------------------
__device__ __forceinline__ uint32_t smem_u32(const void* p) {
    uint32_t a;
    asm("{ .reg .u64 t; cvta.to.shared.u64 t, %1; cvt.u32.u64 %0, t; }" : "=r"(a) : "l"(p));
    return a;
}
#define CP_ASYNC16(dst, src) \
    asm volatile("cp.async.cg.shared.global [%0], [%1], 16;" :: "r"(dst), "l"(src))
#define CP_COMMIT() asm volatile("cp.async.commit_group;" ::: "memory")
#define CP_WAIT2()  asm volatile("cp.async.wait_group 2;" ::: "memory")
#define CP_WAIT1()  asm volatile("cp.async.wait_group 1;" ::: "memory")
#define CP_WAIT0()  asm volatile("cp.async.wait_group 0;" ::: "memory")

__device__ __forceinline__ void ldsm4(uint32_t* r, uint32_t addr) {
    asm volatile("ldmatrix.sync.aligned.m8n8.x4.shared.b16 {%0,%1,%2,%3}, [%4];"
                 : "=r"(r[0]), "=r"(r[1]), "=r"(r[2]), "=r"(r[3]) : "r"(addr));
}
// fp16 inputs, f32 accumulate (single accumulator bank)
__device__ __forceinline__ void mma16816(float* d, const uint32_t* a, const uint32_t* b) {
    asm volatile("mma.sync.aligned.m16n8k16.row.col.f32.f16.f16.f32 "
                 "{%0,%1,%2,%3}, {%4,%5,%6,%7}, {%8,%9}, {%0,%1,%2,%3};"
                 : "+f"(d[0]), "+f"(d[1]), "+f"(d[2]), "+f"(d[3])
                 : "r"(a[0]), "r"(a[1]), "r"(a[2]), "r"(a[3]), "r"(b[0]), "r"(b[1]));
}

// ---------------------------------------------------------------------------
// fp16 multi-phase GEMM (NT), all f32-accumulate:
//   NPH=3: phases { Ah*Bh, Ah*Bl, Al*Bh }
//   NPH=2: phases { Ah*Bh, Ah*Bl }
//   NPH=1: phase  { Ah*Bh }
// Block 128x128, BK=32, 4 warps (64x64 warp tile), 4-stage cp.async.
// EPI: 0 = plain fp32 store to Cf + z*sC (split-K partials; z also offsets A/B);
//      1 = fp16 hi/lo split store; 2 = fp32 + u[m] + v[n];
//      3 = fused scorer: atomicAdd out[r] += invden[r]*sum_c C*(Ws2+region*Ws3)
// ---------------------------------------------------------------------------
#define STAGE_B 20480
#define NSTAGE  4
#define SMEM_GEMM (NSTAGE * STAGE_B)   // 80 KB dynamic

template <int EPI, int NPH>
__global__ __launch_bounds__(128, 2) void gemm3_f16(
    const h16* __restrict__ Ah, const h16* __restrict__ Al,
    const h16* __restrict__ Bh, const h16* __restrict__ Bl,
    float* __restrict__ Cf, h16* __restrict__ Chi, h16* __restrict__ Clo,
    const float* __restrict__ uvec, const float* __restrict__ vvec,
    const float* __restrict__ regionF, const float* __restrict__ WsP,
    float* __restrict__ outP,
    int Kbase, int lda, int ldb, int ldc,
    long sA, long sB, long sC, int uStr, int vStr)
{
    extern __shared__ __align__(16) uint8_t smem_raw[];
    const int tid = threadIdx.x;
    const int wid = tid >> 5, l = tid & 31;
    const int wm = wid >> 1, wn = wid & 1;
    const int blockM = blockIdx.y * 128, blockN = blockIdx.x * 128;
    const int z = blockIdx.z;

    Ah += (long)z * sA;  Al += (long)z * sA;
    Bh += (long)z * sB;  Bl += (long)z * sB;

    const uint32_t smBase = smem_u32(smem_raw);
    const int cpb = Kbase / 32;
    const int NK  = NPH * cpb;

    const uint32_t aF = smBase +
        (uint32_t)((wm * 64 + (l & 15)) * 80 + ((l >> 4) * 16));
    const int bn = (l & 7) + ((l & 16) >> 1);
    const uint32_t bF = smBase + 10240u +
        (uint32_t)((wn * 64 + bn) * 80 + (((l >> 3) & 1) * 16));

    float acc[4][8][4];
#pragma unroll
    for (int i = 0; i < 4; i++)
#pragma unroll
        for (int j = 0; j < 8; j++)
#pragma unroll
            for (int q = 0; q < 4; q++) acc[i][j][q] = 0.f;

    const int lr = tid >> 2, lj = tid & 3;

    auto load_stage = [&](int stage, int kb) {
        const int ph  = kb / cpb;
        const int kbl = kb - ph * cpb;
        const h16* Ap = (NPH == 3 && ph == 2) ? Al : Ah;
        const h16* Bp = (ph == 1) ? Bl : Bh;
        const int k0 = kbl * 32;
        const uint32_t sa = smBase + stage * STAGE_B;
        const uint32_t sb = sa + 10240u;
#pragma unroll
        for (int it = 0; it < 4; it++) {
            const int rr = lr + it * 32;
            const h16* ga = Ap + (long)(blockM + rr) * lda + k0 + lj * 8;
            CP_ASYNC16(sa + (uint32_t)(rr * 80 + lj * 16), ga);
            const h16* gb = Bp + (long)(blockN + rr) * ldb + k0 + lj * 8;
            CP_ASYNC16(sb + (uint32_t)(rr * 80 + lj * 16), gb);
        }
        CP_COMMIT();
    };

    load_stage(0, 0);
    if (NK > 1) load_stage(1, 1);
    if (NK > 2) load_stage(2, 2);

    for (int kb = 0; kb < NK; kb++) {
        if (kb < NK - 2)       CP_WAIT2();
        else if (kb == NK - 2) CP_WAIT1();
        else                   CP_WAIT0();
        __syncthreads();
        if (kb + 3 < NK) load_stage((kb + 3) & 3, kb + 3);

        const uint32_t so = (uint32_t)(kb & 3) * STAGE_B;
#pragma unroll
        for (int ks = 0; ks < 2; ks++) {
            uint32_t af[4][4], bfr[4][4];
#pragma unroll
            for (int i = 0; i < 4; i++)
                ldsm4(af[i], aF + so + (uint32_t)(i * (16 * 80) + ks * 32));
#pragma unroll
            for (int j = 0; j < 4; j++)
                ldsm4(bfr[j], bF + so + (uint32_t)(j * (16 * 80) + ks * 32));
#pragma unroll
            for (int i = 0; i < 4; i++)
#pragma unroll
                for (int j = 0; j < 4; j++) {
                    mma16816(acc[i][2 * j],     af[i], &bfr[j][0]);
                    mma16816(acc[i][2 * j + 1], af[i], &bfr[j][2]);
                }
        }
    }

    // ---- epilogue ----
    const int gid = l >> 2, tig = l & 3;
#pragma unroll
    for (int i = 0; i < 4; i++) {
        const int r0g = blockM + wm * 64 + 16 * i + gid;
        const int r1g = r0g + 8;
        float um0 = 0.f, um1 = 0.f;
        if (EPI == 2 || EPI == 3) {
            um0 = uvec[(long)z * uStr + r0g];
            um1 = uvec[(long)z * uStr + r1g];
        }
        float part0 = 0.f, part1 = 0.f;
#pragma unroll
        for (int jj = 0; jj < 8; jj++) {
            const int c0 = blockN + wn * 64 + 8 * jj + 2 * tig;
            float x0 = acc[i][jj][0], x1 = acc[i][jj][1];
            float x2 = acc[i][jj][2], x3 = acc[i][jj][3];
            if (EPI == 0) {
                float* base = Cf + (long)z * sC;
                *(float2*)&base[(long)r0g * ldc + c0] = make_float2(x0, x1);
                *(float2*)&base[(long)r1g * ldc + c0] = make_float2(x2, x3);
            } else if (EPI == 2) {
                float2 vv = *(const float2*)&vvec[(long)z * vStr + c0];
                x0 += um0 + vv.x;  x1 += um0 + vv.y;
                x2 += um1 + vv.x;  x3 += um1 + vv.y;
                float* base = Cf + (long)z * sC;
                *(float2*)&base[(long)r0g * ldc + c0] = make_float2(x0, x1);
                *(float2*)&base[(long)r1g * ldc + c0] = make_float2(x2, x3);
            } else if (EPI == 1) {
                h16 h0 = __float2half_rn(x0), h1 = __float2half_rn(x1);
                h16 h2 = __float2half_rn(x2), h3 = __float2half_rn(x3);
                h16 l0 = __float2half_rn(x0 - __half2float(h0));
                h16 l1 = __float2half_rn(x1 - __half2float(h1));
                h16 l2 = __float2half_rn(x2 - __half2float(h2));
                h16 l3 = __float2half_rn(x3 - __half2float(h3));
                h16* bh = Chi + (long)z * sC;
                h16* bl = Clo + (long)z * sC;
                *(__half2*)&bh[(long)r0g * ldc + c0] = __halves2half2(h0, h1);
                *(__half2*)&bh[(long)r1g * ldc + c0] = __halves2half2(h2, h3);
                *(__half2*)&bl[(long)r0g * ldc + c0] = __halves2half2(l0, l1);
                *(__half2*)&bl[(long)r1g * ldc + c0] = __halves2half2(l2, l3);
            } else { // EPI == 3 : fused scorer on UNNORMALIZED att
                const float* rgB = regionF + (long)z * RR * DD;
                float2 w2 = *(const float2*)&WsP[DD + c0];
                float2 w3 = *(const float2*)&WsP[2 * DD + c0];
                float2 r0v = *(const float2*)&rgB[(long)r0g * DD + c0];
                float2 r1v = *(const float2*)&rgB[(long)r1g * DD + c0];
                part0 += x0 * (w2.x + r0v.x * w3.x) + x1 * (w2.y + r0v.y * w3.y);
                part1 += x2 * (w2.x + r1v.x * w3.x) + x3 * (w2.y + r1v.y * w3.y);
            }
        }
        if (EPI == 3) {
            part0 += __shfl_xor_sync(0xffffffffu, part0, 1);
            part0 += __shfl_xor_sync(0xffffffffu, part0, 2);
            part1 += __shfl_xor_sync(0xffffffffu, part1, 1);
            part1 += __shfl_xor_sync(0xffffffffu, part1, 2);
            if (tig == 0) {
                atomicAdd(&outP[(long)z * RR + r0g], part0 * um0);  // um = invden
                atomicAdd(&outP[(long)z * RR + r1g], part1 * um1);
            }
        }
    }
}

// ---------------------------------------------------------------------------
// Prep kernels (fp16 splits)
// ---------------------------------------------------------------------------
__global__ __launch_bounds__(256) void split_f16(
    const float* __restrict__ in, h16* __restrict__ h, h16* __restrict__ lo, long n4)
{
    long i = (long)blockIdx.x * blockDim.x + threadIdx.x;
    if (i >= n4) return;
    float4 v = ((const float4*)in)[i];
    h16 h0 = __float2half_rn(v.x), h1 = __float2half_rn(v.y);
    h16 h2 = __float2half_rn(v.z), h3 = __float2half_rn(v.w);
    h16 l0 = __float2half_rn(v.x - __half2float(h0));
    h16 l1 = __float2half_rn(v.y - __half2float(h1));
    h16 l2 = __float2half_rn(v.z - __half2float(h2));
    h16 l3 = __float2half_rn(v.w - __half2float(h3));
    ((__half2*)h )[2 * i]     = __halves2half2(h0, h1);
    ((__half2*)h )[2 * i + 1] = __halves2half2(h2, h3);
    ((__half2*)lo)[2 * i]     = __halves2half2(l0, l1);
    ((__half2*)lo)[2 * i + 1] = __halves2half2(l2, l3);
}

// sum 4 split-K fp32 partials -> fp16 hi/lo
__global__ __launch_bounds__(256) void reduce4_split(
    const float* __restrict__ part, h16* __restrict__ h, h16* __restrict__ lo, long n4)
{
    long i = (long)blockIdx.x * blockDim.x + threadIdx.x;
    if (i >= n4) return;
    float4 a = ((const float4*)part)[i];
    float4 b = ((const float4*)part)[i +     n4];
    float4 c = ((const float4*)part)[i + 2 * n4];
    float4 d = ((const float4*)part)[i + 3 * n4];
    float4 v = make_float4((a.x + b.x) + (c.x + d.x), (a.y + b.y) + (c.y + d.y),
                           (a.z + b.z) + (c.z + d.z), (a.w + b.w) + (c.w + d.w));
    h16 h0 = __float2half_rn(v.x), h1 = __float2half_rn(v.y);
    h16 h2 = __float2half_rn(v.z), h3 = __float2half_rn(v.w);
    h16 l0 = __float2half_rn(v.x - __half2float(h0));
    h16 l1 = __float2half_rn(v.y - __half2float(h1));
    h16 l2 = __float2half_rn(v.z - __half2float(h2));
    h16 l3 = __float2half_rn(v.w - __half2float(h3));
    ((__half2*)h )[2 * i]     = __halves2half2(h0, h1);
    ((__half2*)h )[2 * i + 1] = __halves2half2(h2, h3);
    ((__half2*)lo)[2 * i]     = __halves2half2(l0, l1);
    ((__half2*)lo)[2 * i + 1] = __halves2half2(l2, l3);
}

// fused: blocks 0-127 -> wrbq rows, 128-255 -> wqbr rows, block 256 -> c
__global__ __launch_bounds__(256) void weight_dots(
    const float* __restrict__ Wr, const float* __restrict__ Wq,
    const float* __restrict__ br, const float* __restrict__ bq,
    float* __restrict__ wrbq, float* __restrict__ wqbr, float* __restrict__ cptr)
{
    const int b = blockIdx.x;
    const int lane = threadIdx.x & 31, warp = threadIdx.x >> 5;
    if (b == 256) {
        if (warp == 0) {
            float s = 0.f;
            for (int k = lane; k < HH; k += 32) s += br[k] * bq[k];
#pragma unroll
            for (int o = 16; o > 0; o >>= 1) s += __shfl_xor_sync(0xffffffffu, s, o);
            if (lane == 0) cptr[0] = s;
        }
        return;
    }
    const float* X = (b < 128) ? Wr : Wq;
    const float* w = (b < 128) ? bq : br;
    float* outv    = (b < 128) ? wrbq : wqbr;
    const int row = (b & 127) * 8 + warp;
    const float* x = X + (long)row * HH;
    float s = 0.f;
    for (int k = lane; k < HH; k += 32) s += x[k] * w[k];
#pragma unroll
    for (int o = 16; o > 0; o >>= 1) s += __shfl_xor_sync(0xffffffffu, s, o);
    if (lane == 0) outv[row] = s;
}

__global__ __launch_bounds__(256) void prep_region(
    const float* __restrict__ region, const float* __restrict__ wrbq,
    const float* __restrict__ cptr, const float* __restrict__ Ws,
    const float* __restrict__ bs,
    h16* __restrict__ rh, h16* __restrict__ rl,
    float* __restrict__ u, float* __restrict__ outp)
{
    __shared__ float redA[8], redB[8];
    const long row = blockIdx.x;
    const int tid = threadIdx.x, lane = tid & 31, warp = tid >> 5;

    float4 v = ((const float4*)(region + row * DD))[tid];
    h16 h0 = __float2half_rn(v.x), h1 = __float2half_rn(v.y);
    h16 h2 = __float2half_rn(v.z), h3 = __float2half_rn(v.w);
    h16 l0 = __float2half_rn(v.x - __half2float(h0));
    h16 l1 = __float2half_rn(v.y - __half2float(h1));
    h16 l2 = __float2half_rn(v.z - __half2float(h2));
    h16 l3 = __float2half_rn(v.w - __half2float(h3));
    ((__half2*)(rh + row * DD))[2 * tid]     = __halves2half2(h0, h1);
    ((__half2*)(rh + row * DD))[2 * tid + 1] = __halves2half2(h2, h3);
    ((__half2*)(rl + row * DD))[2 * tid]     = __halves2half2(l0, l1);
    ((__half2*)(rl + row * DD))[2 * tid + 1] = __halves2half2(l2, l3);

    float4 w  = ((const float4*)wrbq)[tid];
    float4 w1 = ((const float4*)Ws  )[tid];
    float du = v.x * w.x  + v.y * w.y  + v.z * w.z  + v.w * w.w;
    float dn = v.x * w1.x + v.y * w1.y + v.z * w1.z + v.w * w1.w;
#pragma unroll
    for (int o = 16; o > 0; o >>= 1) {
        du += __shfl_xor_sync(0xffffffffu, du, o);
        dn += __shfl_xor_sync(0xffffffffu, dn, o);
    }
    if (lane == 0) { redA[warp] = du; redB[warp] = dn; }
    __syncthreads();
    if (tid == 0) {
        float su = 0.f, sn = 0.f;
#pragma unroll
        for (int k = 0; k < 8; k++) { su += redA[k]; sn += redB[k]; }
        u[row]    = su + cptr[0];
        outp[row] = sn + bs[0];
    }
}

__global__ __launch_bounds__(256) void prep_query(
    const float* __restrict__ query, const float* __restrict__ wqbr,
    h16* __restrict__ qh, h16* __restrict__ ql, float* __restrict__ vvec)
{
    __shared__ float red[8];
    const long row = blockIdx.x;
    const int tid = threadIdx.x, lane = tid & 31, warp = tid >> 5;

    float4 v = ((const float4*)(query + row * DD))[tid];
    h16 h0 = __float2half_rn(v.x), h1 = __float2half_rn(v.y);
    h16 h2 = __float2half_rn(v.z), h3 = __float2half_rn(v.w);
    h16 l0 = __float2half_rn(v.x - __half2float(h0));
    h16 l1 = __float2half_rn(v.y - __half2float(h1));
    h16 l2 = __float2half_rn(v.z - __half2float(h2));
    h16 l3 = __float2half_rn(v.w - __half2float(h3));
    ((__half2*)(qh + row * DD))[2 * tid]     = __halves2half2(h0, h1);
    ((__half2*)(qh + row * DD))[2 * tid + 1] = __halves2half2(h2, h3);
    ((__half2*)(ql + row * DD))[2 * tid]     = __halves2half2(l0, l1);
    ((__half2*)(ql + row * DD))[2 * tid + 1] = __halves2half2(l2, l3);

    float4 w = ((const float4*)wqbr)[tid];
    float d = v.x * w.x + v.y * w.y + v.z * w.z + v.w * w.w;
#pragma unroll
    for (int o = 16; o > 0; o >>= 1) d += __shfl_xor_sync(0xffffffffu, d, o);
    if (lane == 0) red[warp] = d;
    __syncthreads();
    if (tid == 0) {
        float s = 0.f;
#pragma unroll
        for (int k = 0; k < 8; k++) s += red[k];
        vvec[row] = s;
    }
}

// query [B][T][D] f32 -> qT_h [B][D][T] fp16 (hi only; att GEMM is 1-phase)
__global__ __launch_bounds__(256) void transpose_h(
    const float* __restrict__ in, h16* __restrict__ oh)
{
    __shared__ float s[32][33];
    const float* ib = in + (long)blockIdx.z * TT * DD;
    h16* oh_b = oh + (long)blockIdx.z * DD * TT;
    const int d0 = blockIdx.x * 32, t0 = blockIdx.y * 32;
    const int tx = threadIdx.x, ty = threadIdx.y;
#pragma unroll
    for (int i = 0; i < 32; i += 8)
        s[ty + i][tx] = ib[(long)(t0 + ty + i) * DD + d0 + tx];
    __syncthreads();
#pragma unroll
    for (int i = 0; i < 32; i += 8)
        oh_b[(long)(d0 + ty + i) * TT + t0 + tx] = __float2half_rn(s[tx][ty + i]);
}

// softmax numerator: exp(x - max) rounded to fp16; invden = 1/sum(rounded exp)
__global__ __launch_bounds__(128) void softmax_exp(
    const float* __restrict__ sc, h16* __restrict__ ae, float* __restrict__ invden)
{
    __shared__ float smax[4];
    __shared__ float ssum[4];
    const long row = blockIdx.x;
    const float4* p = (const float4*)(sc + row * TT);
    const int tid = threadIdx.x;
    const int lane = tid & 31, warp = tid >> 5;

    float4 v = p[tid];
    float m = fmaxf(fmaxf(v.x, v.y), fmaxf(v.z, v.w));
#pragma unroll
    for (int o = 16; o > 0; o >>= 1) m = fmaxf(m, __shfl_xor_sync(0xffffffffu, m, o));
    if (lane == 0) smax[warp] = m;
    __syncthreads();
    m = fmaxf(fmaxf(smax[0], smax[1]), fmaxf(smax[2], smax[3]));

    h16 e0 = __float2half_rn(expf(v.x - m));
    h16 e1 = __float2half_rn(expf(v.y - m));
    h16 e2 = __float2half_rn(expf(v.z - m));
    h16 e3 = __float2half_rn(expf(v.w - m));
    ((__half2*)(ae + row * TT))[2 * tid]     = __halves2half2(e0, e1);
    ((__half2*)(ae + row * TT))[2 * tid + 1] = __halves2half2(e2, e3);

    float s = __half2float(e0) + __half2float(e1)
            + __half2float(e2) + __half2float(e3);
#pragma unroll
    for (int o = 16; o > 0; o >>= 1) s += __shfl_xor_sync(0xffffffffu, s, o);
    if (lane == 0) ssum[warp] = s;
    __syncthreads();
    if (tid == 0)
        invden[row] = 1.0f / (ssum[0] + ssum[1] + ssum[2] + ssum[3]);
}

// ---------------------------------------------------------------------------
extern "C" void kernel_launch(void* const* d_in, const int* in_sizes, int n_in,
                              void* d_out, int out_size)
{
    (void)in_sizes; (void)n_in; (void)out_size;
    const float* region = (const float*)d_in[0];
    const float* query  = (const float*)d_in[1];
    const float* Wr     = (const float*)d_in[2];
    const float* br     = (const float*)d_in[3];
    const float* Wq     = (const float*)d_in[4];
    const float* bq     = (const float*)d_in[5];
    const float* Ws     = (const float*)d_in[6];
    const float* bs     = (const float*)d_in[7];
    float* out = (float*)d_out;

    h16 *region_h, *region_l, *query_h, *query_l;
    h16 *Wr_h, *Wr_l, *Wq_h, *Wq_l, *Mt_h, *Mt_l, *Qp_h, *Qp_l;
    h16 *qT_h, *attn_e;
    float *scores, *invden, *u, *v, *wrbq, *wqbr, *cptr;
    cudaGetSymbolAddress((void**)&region_h, g_region_h);
    cudaGetSymbolAddress((void**)&region_l, g_region_l);
    cudaGetSymbolAddress((void**)&query_h,  g_query_h);
    cudaGetSymbolAddress((void**)&query_l,  g_query_l);
    cudaGetSymbolAddress((void**)&Wr_h, g_Wr_h);
    cudaGetSymbolAddress((void**)&Wr_l, g_Wr_l);
    cudaGetSymbolAddress((void**)&Wq_h, g_Wq_h);
    cudaGetSymbolAddress((void**)&Wq_l, g_Wq_l);
    cudaGetSymbolAddress((void**)&Mt_h, g_Mt_h);
    cudaGetSymbolAddress((void**)&Mt_l, g_Mt_l);
    cudaGetSymbolAddress((void**)&Qp_h, g_Qp_h);
    cudaGetSymbolAddress((void**)&Qp_l, g_Qp_l);
    cudaGetSymbolAddress((void**)&qT_h, g_qT_h);
    cudaGetSymbolAddress((void**)&attn_e, g_attn_e);
    cudaGetSymbolAddress((void**)&scores, g_scores);
    cudaGetSymbolAddress((void**)&invden, g_invden);
    cudaGetSymbolAddress((void**)&u,      g_u);
    cudaGetSymbolAddress((void**)&v,      g_v);
    cudaGetSymbolAddress((void**)&wrbq,   g_wrbq);
    cudaGetSymbolAddress((void**)&wqbr,   g_wqbr);
    cudaGetSymbolAddress((void**)&cptr,   g_c);

    float* Mt_part = scores;   // 4 x DD*DD fp32 partials (dead until step 3)

    cudaFuncSetAttribute((const void*)gemm3_f16<0,3>, cudaFuncAttributeMaxDynamicSharedMemorySize, SMEM_GEMM);
    cudaFuncSetAttribute((const void*)gemm3_f16<1,3>, cudaFuncAttributeMaxDynamicSharedMemorySize, SMEM_GEMM);
    cudaFuncSetAttribute((const void*)gemm3_f16<2,3>, cudaFuncAttributeMaxDynamicSharedMemorySize, SMEM_GEMM);
    cudaFuncSetAttribute((const void*)gemm3_f16<3,1>, cudaFuncAttributeMaxDynamicSharedMemorySize, SMEM_GEMM);

    // weight prep
    split_f16<<<(unsigned)(((long)DD*HH/4 + 255)/256), 256>>>(Wr, Wr_h, Wr_l, (long)DD*HH/4);
    split_f16<<<(unsigned)(((long)DD*HH/4 + 255)/256), 256>>>(Wq, Wq_h, Wq_l, (long)DD*HH/4);
    weight_dots<<<257, 256>>>(Wr, Wq, br, bq, wrbq, wqbr, cptr);

    // fused input prep
    prep_query <<<BB*TT, 256>>>(query, wqbr, query_h, query_l, v);
    prep_region<<<BB*RR, 256>>>(region, wrbq, cptr, Ws, bs, region_h, region_l, u, out);
    transpose_h<<<dim3(DD/32, TT/32, BB), dim3(32, 8)>>>(query, qT_h);

    // 1) Mt2 = Wr @ Wq^T  (fp16x3, split-K x4 -> private fp32 partials, then reduce+split)
    gemm3_f16<0,3><<<dim3(8, 8, 4), 128, SMEM_GEMM>>>(
        Wr_h, Wr_l, Wq_h, Wq_l, Mt_part, nullptr, nullptr, nullptr, nullptr,
        nullptr, nullptr, nullptr,
        /*Kbase=*/HH/4, /*lda=*/HH, /*ldb=*/HH, /*ldc=*/DD,
        /*sA=*/HH/4, /*sB=*/HH/4, /*sC=*/(long)DD*DD, 0, 0);
    reduce4_split<<<(unsigned)(((long)DD*DD/4 + 255)/256), 256>>>(
        Mt_part, Mt_h, Mt_l, (long)DD*DD/4);

    // 2) Qp[b] = query[b] @ Mt2^T  (fp16x3, split out)
    gemm3_f16<1,3><<<dim3(8, 4, BB), 128, SMEM_GEMM>>>(
        query_h, query_l, Mt_h, Mt_l, nullptr, Qp_h, Qp_l, nullptr, nullptr,
        nullptr, nullptr, nullptr,
        DD, DD, DD, DD, (long)TT*DD, 0, (long)TT*DD, 0, 0);

    // 3) scores[b] = region[b] @ Qp[b]^T + u + v  (fp16x3 — full fidelity logits)
    gemm3_f16<2,3><<<dim3(4, 8, BB), 128, SMEM_GEMM>>>(
        region_h, region_l, Qp_h, Qp_l, scores, nullptr, nullptr, u, v,
        nullptr, nullptr, nullptr,
        DD, DD, DD, TT, (long)RR*DD, (long)TT*DD, (long)RR*TT, RR, TT);

    // 4) softmax numerator -> fp16 exp + invden
    softmax_exp<<<BB*RR, 128>>>(scores, attn_e, invden);

    // 5) attU[b] @ qT_h[b]^T  (fp16x1 — post-softmax, error not amplified),
    //    fused scorer epilogue normalizes by invden and atomicAdds into out
    gemm3_f16<3,1><<<dim3(8, 8, BB), 128, SMEM_GEMM>>>(
        attn_e, attn_e, qT_h, qT_h, nullptr, nullptr, nullptr, invden, nullptr,
        region, Ws, out,
        TT, TT, TT, DD, (long)RR*TT, (long)DD*TT, 0, RR, 0);
}